// round 10
// baseline (speedup 1.0000x reference)
#include <cuda_runtime.h>
#include <cuda_fp16.h>

#define NUM_BUCKETS 9311
#define L 8          // categories per (b,c)

// fp16 copy of the embedding table: 9311 rows x 64 ch (128 B/row) = 1.19 MB.
__device__ __half2 g_tab16[NUM_BUCKETS * 32];

// Convert: one float4 -> one uint2 (2 half2) per thread.
__global__ void __launch_bounds__(256)
convert_kernel(const float4* __restrict__ table_f32) {
    int i = blockIdx.x * blockDim.x + threadIdx.x;
    if (i < NUM_BUCKETS * 16) {
        float4 v = table_f32[i];
        __half2 lo = __floats2half2_rn(v.x, v.y);
        __half2 hi = __floats2half2_rn(v.z, v.w);
        uint2 r;
        r.x = *reinterpret_cast<unsigned*>(&lo);
        r.y = *reinterpret_cast<unsigned*>(&hi);
        reinterpret_cast<uint2*>(g_tab16)[i] = r;
    }
}

// Single half2 (4 B) gather with L1 evict_last.
__device__ __forceinline__ __half2 ldg_tab(const __half2* p) {
    unsigned r;
    asm volatile("ld.global.nc.L1::evict_last.u32 %0, [%1];"
                 : "=r"(r) : "l"(p));
    return *reinterpret_cast<__half2*>(&r);
}

// One warp per output row. Every gather: 32 lanes read ONE 128-B table row
// (lane's 4-B chunk) -> exactly one coalesced wavefront per LDG, zero replays.
__global__ void __launch_bounds__(256)
enc_kernel(const int* __restrict__ x,
           float2* __restrict__ out,
           int n_rows) {
    int warp = (blockIdx.x * blockDim.x + threadIdx.x) >> 5;
    int lane = threadIdx.x & 31;
    if (warp >= n_rows) return;          // warp-uniform exit

    // Lanes 0-7 load this row's 8 indices (32 B of a 128-B line; the 4 warps
    // of a block sharing the line hit L1).
    int v = 0;
    if (lane < 8) v = __ldcs(&x[warp * L + lane]);

    unsigned bal = __ballot_sync(0xffffffffu, v > 0);
    int cnt = __popc(bal & 0xFF);

    int h = max(v, 0) % NUM_BUCKETS;     // scalar hash (lanes >=8 compute garbage->0, unused)

    // Broadcast the 8 bucket ids; 8 unconditional single-line gathers
    // (table row 0 is all zeros -> masked entries add 0).
    int h0 = __shfl_sync(0xffffffffu, h, 0);
    int h1 = __shfl_sync(0xffffffffu, h, 1);
    int h2 = __shfl_sync(0xffffffffu, h, 2);
    int h3 = __shfl_sync(0xffffffffu, h, 3);
    int h4 = __shfl_sync(0xffffffffu, h, 4);
    int h5 = __shfl_sync(0xffffffffu, h, 5);
    int h6 = __shfl_sync(0xffffffffu, h, 6);
    int h7 = __shfl_sync(0xffffffffu, h, 7);

    const __half2* tab = g_tab16 + lane;         // lane's chunk within any row
    __half2 g0 = ldg_tab(tab + h0 * 32);
    __half2 g1 = ldg_tab(tab + h1 * 32);
    __half2 g2 = ldg_tab(tab + h2 * 32);
    __half2 g3 = ldg_tab(tab + h3 * 32);
    __half2 g4 = ldg_tab(tab + h4 * 32);
    __half2 g5 = ldg_tab(tab + h5 * 32);
    __half2 g6 = ldg_tab(tab + h6 * 32);
    __half2 g7 = ldg_tab(tab + h7 * 32);

    // 7-op HADD2 tree, widen once, scale in f32.
    __half2 s0 = __hadd2(g0, g1);
    __half2 s1 = __hadd2(g2, g3);
    __half2 s2 = __hadd2(g4, g5);
    __half2 s3 = __hadd2(g6, g7);
    __half2 t  = __hadd2(__hadd2(s0, s1), __hadd2(s2, s3));

    float2 f = __half22float2(t);
    float inv = __fdividef(1.0f, (float)(cnt > 0 ? cnt : 1));

    // Lane l holds channels [2l, 2l+2) -> one contiguous 256-B row store.
    out[(long long)warp * 32 + lane] = make_float2(f.x * inv, f.y * inv);
}

extern "C" void kernel_launch(void* const* d_in, const int* in_sizes, int n_in,
                              void* d_out, int out_size) {
    const int*    xptr = (const int*)d_in[0];
    const float4* tabf = (const float4*)d_in[1];
    float2*       out  = (float2*)d_out;

    // 1) table f32 -> fp16 scratch (idempotent, graph-capturable)
    int n_f4 = NUM_BUCKETS * 16;
    convert_kernel<<<(n_f4 + 255) / 256, 256>>>(tabf);

    // 2) gather: 1 warp per output row, 8 warps/block.
    int n_rows = in_sizes[0] / L;               // B*C = 262144
    int blocks = (n_rows + 7) / 8;              // 32768

    enc_kernel<<<blocks, 256>>>(xptr, out, n_rows);
}

// round 11
// speedup vs baseline: 1.2766x; 1.2766x over previous
#include <cuda_runtime.h>
#include <cuda_fp16.h>

#define NUM_BUCKETS 9311
#define L 8          // categories per (b,c)

// fp16 copy of the embedding table: 9311 rows x 64 ch (128 B/row) = 1.19 MB.
__device__ __half2 g_tab16[NUM_BUCKETS * 32];

// Convert: one float4 -> one uint2 (2 half2) per thread.
__global__ void __launch_bounds__(256)
convert_kernel(const float4* __restrict__ table_f32) {
    int i = blockIdx.x * blockDim.x + threadIdx.x;
    if (i < NUM_BUCKETS * 16) {
        float4 v = table_f32[i];
        __half2 lo = __floats2half2_rn(v.x, v.y);
        __half2 hi = __floats2half2_rn(v.z, v.w);
        uint2 r;
        r.x = *reinterpret_cast<unsigned*>(&lo);
        r.y = *reinterpret_cast<unsigned*>(&hi);
        reinterpret_cast<uint2*>(g_tab16)[i] = r;
    }
    // Signal dependent-launch trigger as soon as this block's writes are issued.
    cudaTriggerProgrammaticLaunchCompletion();
}

// Table gather: LDG.128 with L1 evict_last (bias L1 toward keeping table rows).
__device__ __forceinline__ uint4 ldg_tab(const uint4* p) {
    uint4 r;
    asm volatile("ld.global.nc.L1::evict_last.v4.u32 {%0,%1,%2,%3}, [%4];"
                 : "=r"(r.x), "=r"(r.y), "=r"(r.z), "=r"(r.w) : "l"(p));
    return r;
}

// Streaming store (evict-first in L2): output is written once, never re-read.
__device__ __forceinline__ void stg_cs(float4* p, float4 v) {
    asm volatile("st.global.cs.v4.f32 [%0], {%1,%2,%3,%4};"
                 :: "l"(p), "f"(v.x), "f"(v.y), "f"(v.z), "f"(v.w));
}

__global__ void __launch_bounds__(256)
enc_kernel(const int* __restrict__ x,
           float4* __restrict__ out,
           int n_rows) {
    int warp = (blockIdx.x * blockDim.x + threadIdx.x) >> 5;
    int lane = threadIdx.x & 31;
    int group = lane >> 3;     // 4 rows per warp, 8 lanes per row
    int gl    = lane & 7;      // 16-byte slot within the 128-B fp16 table row

    int row = warp * 4 + group;
    bool valid = (row < n_rows);

    // ── Pre-sync phase: everything that does NOT touch g_tab16. ──
    // One index per lane (128 B coalesced per warp); x read once -> streaming.
    long long xi = (long long)warp * 32 + lane;
    int v = valid ? __ldcs(&x[xi]) : 0;

    int a = max(v, 0);
    int h = a % NUM_BUCKETS;                 // scalar hash per lane

    unsigned bal = __ballot_sync(0xffffffffu, v > 0);
    int cnt = __popc((bal >> (group * 8)) & 0xFF);

    int hb = group << 3;
    int h0 = __shfl_sync(0xffffffffu, h, hb + 0);
    int h1 = __shfl_sync(0xffffffffu, h, hb + 1);
    int h2 = __shfl_sync(0xffffffffu, h, hb + 2);
    int h3 = __shfl_sync(0xffffffffu, h, hb + 3);
    int h4 = __shfl_sync(0xffffffffu, h, hb + 4);
    int h5 = __shfl_sync(0xffffffffu, h, hb + 5);
    int h6 = __shfl_sync(0xffffffffu, h, hb + 6);
    int h7 = __shfl_sync(0xffffffffu, h, hb + 7);

    // ── Wait for convert_kernel's table writes to be visible. ──
    cudaGridDependencySynchronize();

    // 8 LDG.128, front-batched (each fetches 4 table rows, one per group).
    // Unconditional: table row 0 is all zeros -> masked entries add 0.
    const uint4* tab = reinterpret_cast<const uint4*>(g_tab16) + gl;  // row stride = 8 uint4
    uint4 g0 = ldg_tab(tab + h0 * 8);
    uint4 g1 = ldg_tab(tab + h1 * 8);
    uint4 g2 = ldg_tab(tab + h2 * 8);
    uint4 g3 = ldg_tab(tab + h3 * 8);
    uint4 g4 = ldg_tab(tab + h4 * 8);
    uint4 g5 = ldg_tab(tab + h5 * 8);
    uint4 g6 = ldg_tab(tab + h6 * 8);
    uint4 g7 = ldg_tab(tab + h7 * 8);

    // HADD2 tree over 8 gathers x 4 half2 components (28 HADD2).
    #define H2(w) (*reinterpret_cast<const __half2*>(&(w)))
    __half2 s0x = __hadd2(H2(g0.x), H2(g1.x)), s1x = __hadd2(H2(g2.x), H2(g3.x));
    __half2 s2x = __hadd2(H2(g4.x), H2(g5.x)), s3x = __hadd2(H2(g6.x), H2(g7.x));
    __half2 s0y = __hadd2(H2(g0.y), H2(g1.y)), s1y = __hadd2(H2(g2.y), H2(g3.y));
    __half2 s2y = __hadd2(H2(g4.y), H2(g5.y)), s3y = __hadd2(H2(g6.y), H2(g7.y));
    __half2 s0z = __hadd2(H2(g0.z), H2(g1.z)), s1z = __hadd2(H2(g2.z), H2(g3.z));
    __half2 s2z = __hadd2(H2(g4.z), H2(g5.z)), s3z = __hadd2(H2(g6.z), H2(g7.z));
    __half2 s0w = __hadd2(H2(g0.w), H2(g1.w)), s1w = __hadd2(H2(g2.w), H2(g3.w));
    __half2 s2w = __hadd2(H2(g4.w), H2(g5.w)), s3w = __hadd2(H2(g6.w), H2(g7.w));
    __half2 tx = __hadd2(__hadd2(s0x, s1x), __hadd2(s2x, s3x));
    __half2 ty = __hadd2(__hadd2(s0y, s1y), __hadd2(s2y, s3y));
    __half2 tz = __hadd2(__hadd2(s0z, s1z), __hadd2(s2z, s3z));
    __half2 tw = __hadd2(__hadd2(s0w, s1w), __hadd2(s2w, s3w));
    #undef H2

    float2 fx = __half22float2(tx);
    float2 fy = __half22float2(ty);
    float2 fz = __half22float2(tz);
    float2 fw = __half22float2(tw);

    float inv = __fdividef(1.0f, (float)(cnt > 0 ? cnt : 1));
    float4 r0 = make_float4(fx.x * inv, fx.y * inv, fy.x * inv, fy.y * inv);
    float4 r1 = make_float4(fz.x * inv, fz.y * inv, fw.x * inv, fw.y * inv);

    // Lane gl holds channels [8*gl, 8*gl+8) -> float4 slots 2*gl and 2*gl+1.
    if (valid) {
        float4* orow = out + (long long)row * 16 + gl * 2;
        stg_cs(orow + 0, r0);
        stg_cs(orow + 1, r1);
    }
}

extern "C" void kernel_launch(void* const* d_in, const int* in_sizes, int n_in,
                              void* d_out, int out_size) {
    const int*    xptr = (const int*)d_in[0];
    const float4* tabf = (const float4*)d_in[1];
    float4*       out  = (float4*)d_out;

    // 1) table f32 -> fp16 scratch (idempotent, graph-capturable)
    int n_f4 = NUM_BUCKETS * 16;
    convert_kernel<<<(n_f4 + 255) / 256, 256>>>(tabf);

    // 2) gather kernel, launched with programmatic dependent launch so its
    //    x-load/hash prologue overlaps convert_kernel's tail.
    int n_rows = in_sizes[0] / L;        // B*C = 262144
    int blocks = (n_rows + 31) / 32;     // 8192 (32 rows/block)

    cudaLaunchConfig_t cfg = {};
    cfg.gridDim  = dim3((unsigned)blocks);
    cfg.blockDim = dim3(256);
    cfg.dynamicSmemBytes = 0;
    cfg.stream = 0;   // legacy default stream (the captured one)
    cudaLaunchAttribute attrs[1];
    attrs[0].id = cudaLaunchAttributeProgrammaticStreamSerialization;
    attrs[0].val.programmaticStreamSerializationAllowed = 1;
    cfg.attrs = attrs;
    cfg.numAttrs = 1;
    cudaLaunchKernelEx(&cfg, enc_kernel, xptr, out, n_rows);
}

// round 12
// speedup vs baseline: 1.4159x; 1.1091x over previous
#include <cuda_runtime.h>
#include <cuda_fp16.h>

#define NUM_BUCKETS 9311
#define L 8          // categories per (b,c)

// fp16 copy of the embedding table: 9311 rows x 64 ch (128 B/row) = 1.19 MB.
__device__ __half2 g_tab16[NUM_BUCKETS * 32];

// Convert: one float4 -> one uint2 (2 half2) per thread.
__global__ void __launch_bounds__(256)
convert_kernel(const float4* __restrict__ table_f32) {
    int i = blockIdx.x * blockDim.x + threadIdx.x;
    if (i < NUM_BUCKETS * 16) {
        float4 v = table_f32[i];
        __half2 lo = __floats2half2_rn(v.x, v.y);
        __half2 hi = __floats2half2_rn(v.z, v.w);
        uint2 r;
        r.x = *reinterpret_cast<unsigned*>(&lo);
        r.y = *reinterpret_cast<unsigned*>(&hi);
        reinterpret_cast<uint2*>(g_tab16)[i] = r;
    }
    cudaTriggerProgrammaticLaunchCompletion();
}

// Table gather: LDG.128 with L1 evict_last (bias L1 toward keeping table rows).
__device__ __forceinline__ uint4 ldg_tab(const uint4* p) {
    uint4 r;
    asm volatile("ld.global.nc.L1::evict_last.v4.u32 {%0,%1,%2,%3}, [%4];"
                 : "=r"(r.x), "=r"(r.y), "=r"(r.z), "=r"(r.w) : "l"(p));
    return r;
}

__global__ void __launch_bounds__(256)
enc_kernel(const int* __restrict__ x,
           float4* __restrict__ out,
           int n_rows) {
    // Block-local staging for 32 output rows (32 x 256 B = 8 KB), written to
    // gmem with ONE cp.async.bulk per block (no per-lane STG on the LSU).
    __shared__ float4 s_out[512];

    int warp = (blockIdx.x * blockDim.x + threadIdx.x) >> 5;
    int lane = threadIdx.x & 31;
    int group = lane >> 3;     // 4 rows per warp, 8 lanes per row
    int gl    = lane & 7;      // 16-byte slot within the 128-B fp16 table row

    int row = warp * 4 + group;
    bool valid = (row < n_rows);

    // ── Pre-sync phase (independent of g_tab16) ──
    long long xi = (long long)warp * 32 + lane;
    int v = valid ? __ldcs(&x[xi]) : 0;

    int a = max(v, 0);
    int h = a % NUM_BUCKETS;                 // scalar hash per lane

    unsigned bal = __ballot_sync(0xffffffffu, v > 0);
    int cnt = __popc((bal >> (group * 8)) & 0xFF);

    int hb = group << 3;
    int h0 = __shfl_sync(0xffffffffu, h, hb + 0);
    int h1 = __shfl_sync(0xffffffffu, h, hb + 1);
    int h2 = __shfl_sync(0xffffffffu, h, hb + 2);
    int h3 = __shfl_sync(0xffffffffu, h, hb + 3);
    int h4 = __shfl_sync(0xffffffffu, h, hb + 4);
    int h5 = __shfl_sync(0xffffffffu, h, hb + 5);
    int h6 = __shfl_sync(0xffffffffu, h, hb + 6);
    int h7 = __shfl_sync(0xffffffffu, h, hb + 7);

    // Wait for convert_kernel's table writes (PDL).
    cudaGridDependencySynchronize();

    // 8 LDG.128, front-batched (each fetches 4 table rows, one per group).
    // Unconditional: table row 0 is all zeros -> masked entries add 0.
    const uint4* tab = reinterpret_cast<const uint4*>(g_tab16) + gl;  // row stride = 8 uint4
    uint4 g0 = ldg_tab(tab + h0 * 8);
    uint4 g1 = ldg_tab(tab + h1 * 8);
    uint4 g2 = ldg_tab(tab + h2 * 8);
    uint4 g3 = ldg_tab(tab + h3 * 8);
    uint4 g4 = ldg_tab(tab + h4 * 8);
    uint4 g5 = ldg_tab(tab + h5 * 8);
    uint4 g6 = ldg_tab(tab + h6 * 8);
    uint4 g7 = ldg_tab(tab + h7 * 8);

    // HADD2 tree over 8 gathers x 4 half2 components (28 HADD2).
    #define H2(w) (*reinterpret_cast<const __half2*>(&(w)))
    __half2 s0x = __hadd2(H2(g0.x), H2(g1.x)), s1x = __hadd2(H2(g2.x), H2(g3.x));
    __half2 s2x = __hadd2(H2(g4.x), H2(g5.x)), s3x = __hadd2(H2(g6.x), H2(g7.x));
    __half2 s0y = __hadd2(H2(g0.y), H2(g1.y)), s1y = __hadd2(H2(g2.y), H2(g3.y));
    __half2 s2y = __hadd2(H2(g4.y), H2(g5.y)), s3y = __hadd2(H2(g6.y), H2(g7.y));
    __half2 s0z = __hadd2(H2(g0.z), H2(g1.z)), s1z = __hadd2(H2(g2.z), H2(g3.z));
    __half2 s2z = __hadd2(H2(g4.z), H2(g5.z)), s3z = __hadd2(H2(g6.z), H2(g7.z));
    __half2 s0w = __hadd2(H2(g0.w), H2(g1.w)), s1w = __hadd2(H2(g2.w), H2(g3.w));
    __half2 s2w = __hadd2(H2(g4.w), H2(g5.w)), s3w = __hadd2(H2(g6.w), H2(g7.w));
    __half2 tx = __hadd2(__hadd2(s0x, s1x), __hadd2(s2x, s3x));
    __half2 ty = __hadd2(__hadd2(s0y, s1y), __hadd2(s2y, s3y));
    __half2 tz = __hadd2(__hadd2(s0z, s1z), __hadd2(s2z, s3z));
    __half2 tw = __hadd2(__hadd2(s0w, s1w), __hadd2(s2w, s3w));
    #undef H2

    float2 fx = __half22float2(tx);
    float2 fy = __half22float2(ty);
    float2 fz = __half22float2(tz);
    float2 fw = __half22float2(tw);

    float inv = __fdividef(1.0f, (float)(cnt > 0 ? cnt : 1));
    float4 r0 = make_float4(fx.x * inv, fx.y * inv, fy.x * inv, fy.y * inv);
    float4 r1 = make_float4(fz.x * inv, fz.y * inv, fw.x * inv, fw.y * inv);

    // Stage in SMEM (STS.128 x2, issue-only cost).
    int lrow = ((threadIdx.x >> 5) << 2) + group;         // 0..31
    s_out[lrow * 16 + gl * 2 + 0] = r0;
    s_out[lrow * 16 + gl * 2 + 1] = r1;
    __syncthreads();

    int first_row = blockIdx.x * 32;
    bool full_block = (first_row + 32 <= n_rows);
    if (full_block) {
        // One 8 KB bulk store per block via the TMA/bulk pipe.
        asm volatile("fence.proxy.async.shared::cta;" ::: "memory");
        if (threadIdx.x == 0) {
            unsigned saddr;
            asm("{ .reg .u64 t; cvta.to.shared.u64 t, %1; cvt.u32.u64 %0, t; }"
                : "=r"(saddr) : "l"(s_out));
            float4* dst = out + (long long)first_row * 16;
            asm volatile("cp.async.bulk.global.shared::cta.bulk_group [%0], [%1], %2;"
                         :: "l"(dst), "r"(saddr), "n"(8192) : "memory");
            asm volatile("cp.async.bulk.commit_group;" ::: "memory");
            asm volatile("cp.async.bulk.wait_group.read 0;" ::: "memory");
        }
    } else if (valid) {
        // Tail fallback (not hit for these shapes).
        float4* orow = out + (long long)row * 16 + gl * 2;
        orow[0] = r0;
        orow[1] = r1;
    }
}

extern "C" void kernel_launch(void* const* d_in, const int* in_sizes, int n_in,
                              void* d_out, int out_size) {
    const int*    xptr = (const int*)d_in[0];
    const float4* tabf = (const float4*)d_in[1];
    float4*       out  = (float4*)d_out;

    // 1) table f32 -> fp16 scratch (idempotent, graph-capturable)
    int n_f4 = NUM_BUCKETS * 16;
    convert_kernel<<<(n_f4 + 255) / 256, 256>>>(tabf);

    // 2) gather kernel with PDL so its x-load/hash prologue overlaps convert.
    int n_rows = in_sizes[0] / L;        // B*C = 262144
    int blocks = (n_rows + 31) / 32;     // 8192 (32 rows/block)

    cudaLaunchConfig_t cfg = {};
    cfg.gridDim  = dim3((unsigned)blocks);
    cfg.blockDim = dim3(256);
    cfg.dynamicSmemBytes = 0;
    cfg.stream = 0;
    cudaLaunchAttribute attrs[1];
    attrs[0].id = cudaLaunchAttributeProgrammaticStreamSerialization;
    attrs[0].val.programmaticStreamSerializationAllowed = 1;
    cfg.attrs = attrs;
    cfg.numAttrs = 1;
    cudaLaunchKernelEx(&cfg, enc_kernel, xptr, out, n_rows);
}